// round 15
// baseline (speedup 1.0000x reference)
#include <cuda_runtime.h>
#include <cuda_bf16.h>
#include <cstdint>

#define TPB 256
#define GM 2048
#define GN 16384
#define GK 3072

#define BM 128
#define BN 128
#define BK 64
#define NKT (GK / BK)           // 48
#define A_TILE_B (BM * 128)
#define B_TILE_B (BN * 128)
#define STG_B (A_TILE_B + B_TILE_B)
#define GEMM_SMEM (3 * STG_B)   // 98304 -> 2 CTAs/SM

// topk_rerank smem layout (bytes)
#define SM_XS   0
#define SM_SU   12288
#define SM_HIST (12288 + 65536)        // 77824
#define SM_KEY  (SM_HIST + 8192)       // 86016
#define SM_CIDX (SM_KEY + 2048)        // 88064
#define SM_SCAN (SM_CIDX + 1024)       // 89088
#define SMEM_TOPK (SM_SCAN + 1024)     // 90112

__device__ float g_pre[(size_t)GM * GN];
__device__ float g_Bt[(size_t)GN * GK];
__device__ __nv_bfloat16 g_Btb[(size_t)GN * GK];
__device__ __nv_bfloat16 g_Ab[(size_t)GM * GK];
__device__ int   g_topk_idx[GM * 256];
__device__ float g_topk_val[GM * 256];
__device__ float g_partial[GM];

// ---------------- helpers ----------------
__device__ __forceinline__ void mma_bf16(float* c, const uint32_t* a, const uint32_t* b) {
    asm volatile(
        "mma.sync.aligned.m16n8k16.row.col.f32.bf16.bf16.f32 "
        "{%0,%1,%2,%3}, {%4,%5,%6,%7}, {%8,%9}, {%0,%1,%2,%3};"
        : "+f"(c[0]), "+f"(c[1]), "+f"(c[2]), "+f"(c[3])
        : "r"(a[0]), "r"(a[1]), "r"(a[2]), "r"(a[3]), "r"(b[0]), "r"(b[1]));
}
__device__ __forceinline__ void ldsm_x4(uint32_t& r0, uint32_t& r1, uint32_t& r2,
                                        uint32_t& r3, uint32_t addr) {
    asm volatile("ldmatrix.sync.aligned.m8n8.x4.shared.b16 {%0,%1,%2,%3}, [%4];"
                 : "=r"(r0), "=r"(r1), "=r"(r2), "=r"(r3) : "r"(addr));
}
__device__ __forceinline__ void bulk_g2s(uint32_t dst, const void* src,
                                         uint32_t bytes, uint32_t bar) {
    asm volatile(
        "cp.async.bulk.shared::cluster.global.mbarrier::complete_tx::bytes "
        "[%0], [%1], %2, [%3];"
        :: "r"(dst), "l"(src), "r"(bytes), "r"(bar) : "memory");
}
__device__ __forceinline__ uint32_t smem_u32(const void* p) {
    uint32_t a;
    asm("{ .reg .u64 t; cvta.to.shared.u64 t, %1; cvt.u32.u64 %0, t; }" : "=r"(a) : "l"(p));
    return a;
}
__device__ __forceinline__ void mbar_init(uint32_t a, uint32_t c) {
    asm volatile("mbarrier.init.shared.b64 [%0], %1;" :: "r"(a), "r"(c) : "memory");
}
__device__ __forceinline__ void mbar_expect_tx(uint32_t a, uint32_t bytes) {
    asm volatile("mbarrier.arrive.expect_tx.shared.b64 _, [%0], %1;" :: "r"(a), "r"(bytes) : "memory");
}
__device__ __forceinline__ void mbar_arrive(uint32_t a) {
    asm volatile("mbarrier.arrive.shared.b64 _, [%0];" :: "r"(a) : "memory");
}
__device__ __forceinline__ void mbar_wait(uint32_t a, uint32_t parity) {
    asm volatile(
        "{\n\t.reg .pred P;\nW_%=:\n\t"
        "mbarrier.try_wait.parity.acquire.cta.shared::cta.b64 P, [%0], %1, 0x989680;\n\t"
        "@P bra.uni D_%=;\n\tbra.uni W_%=;\nD_%=:\n\t}"
        :: "r"(a), "r"(parity) : "memory");
}
__device__ __forceinline__ void mbar_wait_rlx(uint32_t a, uint32_t parity) {
    asm volatile(
        "{\n\t.reg .pred P;\nW_%=:\n\t"
        "mbarrier.try_wait.parity.relaxed.cta.shared::cta.b64 P, [%0], %1, 0x989680;\n\t"
        "@P bra.uni D_%=;\n\tbra.uni W_%=;\nD_%=:\n\t}"
        :: "r"(a), "r"(parity) : "memory");
}
__device__ __forceinline__ unsigned f2ord(float f) {
    unsigned u = __float_as_uint(f);
    return (u & 0x80000000u) ? ~u : (u | 0x80000000u);
}
__device__ __forceinline__ float ord2f(unsigned o) {
    unsigned u = (o & 0x80000000u) ? (o & 0x7FFFFFFFu) : ~o;
    return __uint_as_float(u);
}
__device__ __forceinline__ void kah(float& s, float& c, float p) {
    float y = __fsub_rn(p, c);
    float t = __fadd_rn(s, y);
    c = __fsub_rn(__fsub_rn(t, s), y);
    s = t;
}
__device__ __forceinline__ uint32_t pack_bf2(float a, float b) {
    __nv_bfloat162 h = __floats2bfloat162_rn(a, b);
    return *(uint32_t*)&h;
}

// ---------------- prep: A conv (bf16 tiled) + W_enc transpose (fp32 + bf16) -
__global__ __launch_bounds__(256)
void prep_kernel(const float* __restrict__ x, const float* __restrict__ W) {
    __shared__ float t[32][33];
    const int n0 = blockIdx.x * 32, k0 = blockIdx.y * 32;
    const int tx = threadIdx.x, ty = threadIdx.y;
    const int tid = ty * 32 + tx;
    const int bid = blockIdx.y * gridDim.x + blockIdx.x;

    {
        const int nch = GM * GK / 8;
        int i = bid * 256 + tid;
        if (i < nch) {
            int m = i / (GK / 8);
            int kc8 = i - m * (GK / 8);
            const float4* src = (const float4*)(x + (size_t)m * GK + kc8 * 8);
            float4 v0 = src[0], v1 = src[1];
            uint4 p = make_uint4(pack_bf2(v0.x, v0.y), pack_bf2(v0.z, v0.w),
                                 pack_bf2(v1.x, v1.y), pack_bf2(v1.z, v1.w));
            int m_blk = m >> 7, row = m & 127;
            int k_blk = kc8 >> 3, ch = kc8 & 7;
            size_t off = ((size_t)(m_blk * NKT + k_blk) * 128 + row) * 128
                       + ((ch ^ (row & 7)) << 4);
            *(uint4*)((char*)g_Ab + off) = p;
        }
    }

#pragma unroll
    for (int i = 0; i < 4; i++)
        t[ty + i * 8][tx] = W[(size_t)(k0 + ty + i * 8) * GN + n0 + tx];
    __syncthreads();
#pragma unroll
    for (int i = 0; i < 4; i++)
        g_Bt[(size_t)(n0 + ty + i * 8) * GK + k0 + tx] = t[tx][ty + i * 8];

    char* dst = (char*)g_Btb;
    for (int it = tid; it < 32 * 4; it += 256) {
        int nl = it >> 2, c = it & 3;
        int n = n0 + nl;
        uint32_t w[4];
#pragma unroll
        for (int j = 0; j < 4; j++)
            w[j] = pack_bf2(t[c * 8 + j * 2][nl], t[c * 8 + j * 2 + 1][nl]);
        int n_blk = n >> 7, row = n & 127;
        int k_blk = k0 >> 6;
        int ch = ((k0 & 63) >> 3) + c;
        size_t off = ((size_t)(n_blk * NKT + k_blk) * 128 + row) * 128
                   + ((ch ^ (row & 7)) << 4);
        *(uint4*)(dst + off) = make_uint4(w[0], w[1], w[2], w[3]);
    }
}

// ---------------- coarse GEMM (R10-proven: 435us, tensor 78%) ---------------
__global__ __launch_bounds__(256, 2)
void mma_gemm_kernel()
{
    extern __shared__ char smc[];
    __shared__ uint64_t barmem[6];
    const uint32_t sb = smem_u32(smc);
    const uint32_t bb = smem_u32(barmem);
    const int tid = threadIdx.x;
    const int lane = tid & 31;
    const int wid = tid >> 5;
    const int wm = wid & 1;
    const int wn = wid >> 1;

    if (tid == 0) {
#pragma unroll
        for (int s = 0; s < 3; s++) {
            mbar_init(bb + s * 8, 1);
            mbar_init(bb + 24 + s * 8, 256);
        }
    }
    __syncthreads();

    const char* Ag = (const char*)g_Ab + (size_t)blockIdx.x * NKT * A_TILE_B;
    const char* Bg = (const char*)g_Btb + (size_t)blockIdx.y * NKT * B_TILE_B;

    if (tid == 0) {
#pragma unroll
        for (int kt = 0; kt < 3; kt++) {
            mbar_expect_tx(bb + kt * 8, STG_B);
            bulk_g2s(sb + kt * STG_B, Ag + (size_t)kt * A_TILE_B, A_TILE_B, bb + kt * 8);
            bulk_g2s(sb + kt * STG_B + A_TILE_B, Bg + (size_t)kt * B_TILE_B, B_TILE_B, bb + kt * 8);
        }
    }

    float acc[4][4][4];
#pragma unroll
    for (int i = 0; i < 4; i++)
#pragma unroll
        for (int j = 0; j < 4; j++)
#pragma unroll
            for (int q = 0; q < 4; q++) acc[i][j][q] = 0.0f;

    uint32_t arow[4], brow[2];
#pragma unroll
    for (int mi = 0; mi < 4; mi++) {
        int r = wm * 64 + mi * 16 + (lane & 15);
        arow[mi] = (uint32_t)(r * 128) | ((uint32_t)(r & 7) << 24);
    }
#pragma unroll
    for (int nj = 0; nj < 2; nj++) {
        int r = wn * 32 + nj * 16 + (lane & 7) + ((lane >> 4) << 3);
        brow[nj] = (uint32_t)(r * 128) | ((uint32_t)(r & 7) << 24);
    }
    const uint32_t achunk = (uint32_t)(lane >> 4);
    const uint32_t bchunk = (uint32_t)((lane >> 3) & 1);

    for (int kt = 0; kt < NKT; kt++) {
        const int s = kt - (kt / 3) * 3;
        const int u = kt / 3;
        mbar_wait(bb + s * 8, u & 1);

        const uint32_t Ab = sb + s * STG_B;
        const uint32_t Bb = Ab + A_TILE_B;

#pragma unroll
        for (int ks = 0; ks < 4; ks++) {
            uint32_t af[4][4], bf[4][2];
#pragma unroll
            for (int mi = 0; mi < 4; mi++) {
                uint32_t swz = arow[mi] >> 24;
                uint32_t ch = (uint32_t)(ks * 2) + achunk;
                uint32_t addr = Ab + (arow[mi] & 0xFFFFFFu) + ((ch ^ swz) << 4);
                ldsm_x4(af[mi][0], af[mi][1], af[mi][2], af[mi][3], addr);
            }
#pragma unroll
            for (int nj = 0; nj < 2; nj++) {
                uint32_t swz = brow[nj] >> 24;
                uint32_t ch = (uint32_t)(ks * 2) + bchunk;
                uint32_t addr = Bb + (brow[nj] & 0xFFFFFFu) + ((ch ^ swz) << 4);
                ldsm_x4(bf[nj * 2][0], bf[nj * 2][1], bf[nj * 2 + 1][0], bf[nj * 2 + 1][1], addr);
            }
#pragma unroll
            for (int mi = 0; mi < 4; mi++)
#pragma unroll
                for (int ni = 0; ni < 4; ni++)
                    mma_bf16(acc[mi][ni], af[mi], bf[ni]);
        }

        mbar_arrive(bb + 24 + s * 8);
        if (tid == 0 && kt + 3 < NKT) {
            mbar_wait_rlx(bb + 24 + s * 8, u & 1);
            mbar_expect_tx(bb + s * 8, STG_B);
            bulk_g2s(sb + s * STG_B, Ag + (size_t)(kt + 3) * A_TILE_B, A_TILE_B, bb + s * 8);
            bulk_g2s(sb + s * STG_B + A_TILE_B, Bg + (size_t)(kt + 3) * B_TILE_B, B_TILE_B, bb + s * 8);
        }
    }

    const int m0 = blockIdx.x * BM, n0 = blockIdx.y * BN;
#pragma unroll
    for (int mi = 0; mi < 4; mi++)
#pragma unroll
        for (int ni = 0; ni < 4; ni++) {
            int r = m0 + wm * 64 + mi * 16 + (lane >> 2);
            int c = n0 + wn * 32 + ni * 8 + (lane & 3) * 2;
            *(float2*)(g_pre + (size_t)r * GN + c) = make_float2(acc[mi][ni][0], acc[mi][ni][1]);
            *(float2*)(g_pre + (size_t)(r + 8) * GN + c) = make_float2(acc[mi][ni][2], acc[mi][ni][3]);
        }
}

// ---------------- z zeroing (slot 2) ----------------
__global__ __launch_bounds__(256)
void zzero_kernel(float* __restrict__ z) {
    const size_t n = (size_t)GM * GN;
    for (size_t i = (size_t)blockIdx.x * blockDim.x + threadIdx.x; i < n;
         i += (size_t)gridDim.x * blockDim.x)
        z[i] = 0.0f;
}

// ---------------- fused 2-level-histogram select + index-sorted rerank ------
__global__ __launch_bounds__(TPB)
void topk_rerank_kernel(const float* __restrict__ x, const float* __restrict__ bias,
                        const int* __restrict__ kptr, float* __restrict__ z)
{
    extern __shared__ __align__(16) char sm[];
    float*    xs   = (float*)(sm + SM_XS);        // 3072 f32
    unsigned* su   = (unsigned*)(sm + SM_SU);     // 16384 ordered keys
    unsigned* hist = (unsigned*)(sm + SM_HIST);   // 2048 bins
    unsigned long long* key = (unsigned long long*)(sm + SM_KEY);  // 256
    int*      cidx = (int*)(sm + SM_CIDX);        // 256
    int*      scan = (int*)(sm + SM_SCAN);        // 256
    __shared__ int sT1, sC1, sT2, sC2, sCnt2, sNgt, sNmid, sNeq;

    const int b = blockIdx.x;
    const int tid = threadIdx.x;
    const int lane = tid & 31;
    const int wrp = tid >> 5;
    const int k = kptr[0];
    const int kc = min(k + 32, 256);

#pragma unroll
    for (int q = 0; q < 8; q++) hist[tid + q * 256] = 0u;
    key[tid] = 0ull;
    if (tid == 0) { sNgt = 0; sNmid = 0; sNeq = 0; }
    {
        const float4* xg = (const float4*)(x + (size_t)b * GK);
#pragma unroll
        for (int q = 0; q < 3; q++) ((float4*)xs)[tid + 256 * q] = xg[tid + 256 * q];
    }
    __syncthreads();

    // pass 1: keys -> smem + level-1 histogram (top 11 bits)
    {
        const float4* row4 = (const float4*)(g_pre + (size_t)b * GN);
        const float4* b4 = (const float4*)bias;
#pragma unroll
        for (int q = 0; q < 16; q++) {
            int i4 = tid + q * 256;
            float4 r = row4[i4];
            float4 bb = __ldg(&b4[i4]);
            unsigned u0 = f2ord(r.x + bb.x);
            unsigned u1 = f2ord(r.y + bb.y);
            unsigned u2 = f2ord(r.z + bb.z);
            unsigned u3 = f2ord(r.w + bb.w);
            ((uint4*)su)[i4] = make_uint4(u0, u1, u2, u3);
            atomicAdd(&hist[u0 >> 21], 1u);
            atomicAdd(&hist[u1 >> 21], 1u);
            atomicAdd(&hist[u2 >> 21], 1u);
            atomicAdd(&hist[u3 >> 21], 1u);
        }
    }
    __syncthreads();

    // level-1 threshold bin T1
    {
        int s = 0;
#pragma unroll
        for (int j = 0; j < 8; j++) s += (int)hist[2047 - 8 * tid - j];
        scan[tid] = s;
    }
    __syncthreads();
    if (tid == 0) {
        int acc = 0;
        for (int t = 0; t < 256; t++) { int v = scan[t]; scan[t] = acc; acc += v; }
    }
    __syncthreads();
    {
        int cum = scan[tid];
#pragma unroll
        for (int j = 0; j < 8; j++) {
            int bn = 2047 - 8 * tid - j;
            int c = (int)hist[bn];
            if (cum < kc && cum + c >= kc) { sT1 = bn; sC1 = cum; }
            cum += c;
        }
    }
    __syncthreads();
    const unsigned T1 = (unsigned)sT1;
    const int C1 = sC1;
    const int need2 = kc - C1;   // >= 1

    // pass 1b: level-2 histogram over bucket-T1 elements (bits 20:10)
#pragma unroll
    for (int q = 0; q < 8; q++) hist[tid + q * 256] = 0u;
    __syncthreads();
#pragma unroll
    for (int q = 0; q < 16; q++) {
        uint4 u = ((uint4*)su)[tid + q * 256];
        if ((u.x >> 21) == T1) atomicAdd(&hist[(u.x >> 10) & 2047u], 1u);
        if ((u.y >> 21) == T1) atomicAdd(&hist[(u.y >> 10) & 2047u], 1u);
        if ((u.z >> 21) == T1) atomicAdd(&hist[(u.z >> 10) & 2047u], 1u);
        if ((u.w >> 21) == T1) atomicAdd(&hist[(u.w >> 10) & 2047u], 1u);
    }
    __syncthreads();

    // level-2 threshold sub-bin T2
    {
        int s = 0;
#pragma unroll
        for (int j = 0; j < 8; j++) s += (int)hist[2047 - 8 * tid - j];
        scan[tid] = s;
    }
    __syncthreads();
    if (tid == 0) {
        int acc = 0;
        for (int t = 0; t < 256; t++) { int v = scan[t]; scan[t] = acc; acc += v; }
    }
    __syncthreads();
    {
        int cum = scan[tid];
#pragma unroll
        for (int j = 0; j < 8; j++) {
            int bn = 2047 - 8 * tid - j;
            int c = (int)hist[bn];
            if (cum < need2 && cum + c >= need2) { sT2 = bn; sC2 = cum; sCnt2 = c; }
            cum += c;
        }
    }
    __syncthreads();
    const unsigned T2 = (unsigned)sT2;
    const int C2 = sC2;
    const int kact = min(C1 + C2 + sCnt2, 256);
    const int cap_eq = kact - C1 - C2;

    // pass 2: compaction (>T1 | T1&&>T2 | T1&&==T2 capped)
#pragma unroll
    for (int q = 0; q < 16; q++) {
        int i4 = tid + q * 256;
        uint4 u = ((uint4*)su)[i4];
        int e0 = i4 * 4;
        unsigned uu[4] = { u.x, u.y, u.z, u.w };
#pragma unroll
        for (int e = 0; e < 4; e++) {
            unsigned bn = uu[e] >> 21;
            if (bn > T1) cidx[atomicAdd(&sNgt, 1)] = e0 + e;
            else if (bn == T1) {
                unsigned sub = (uu[e] >> 10) & 2047u;
                if (sub > T2) cidx[C1 + atomicAdd(&sNmid, 1)] = e0 + e;
                else if (sub == T2) {
                    int er = atomicAdd(&sNeq, 1);
                    if (er < cap_eq) cidx[C1 + C2 + er] = e0 + e;
                }
            }
        }
    }
    __syncthreads();

    // sort candidates by feature index ascending -> all 2048 blocks sweep g_Bt
    // in roughly lockstep order: random DRAM gather becomes L2-windowed reuse.
    // (rerank order is irrelevant for correctness; value-sort follows.)
    {
        int myc = (tid < kact) ? cidx[tid] : 0x7FFFFFFF;
        cidx[tid] = myc;
    }
    __syncthreads();
    for (int kk = 2; kk <= 256; kk <<= 1) {
        for (int j = kk >> 1; j > 0; j >>= 1) {
            int ixj = tid ^ j;
            if (ixj > tid) {
                int a = cidx[tid], bb2 = cidx[ixj];
                bool up = ((tid & kk) == 0);
                if (up ? (a > bb2) : (a < bb2)) { cidx[tid] = bb2; cidx[ixj] = a; }
            }
            __syncthreads();
        }
    }

    // exact rerank of kact candidates (Kahan fp32 + double reduce)
    const float4* xs4 = (const float4*)xs;
    for (int c = wrp; c < kact; c += 8) {
        const int fi = cidx[c];
        const float4* wr = (const float4*)(g_Bt + (size_t)fi * GK);
        float s = 0.0f, comp = 0.0f;
#pragma unroll 4
        for (int it = 0; it < 24; it++) {
            int j = lane + it * 32;
            float4 wv = wr[j];
            float4 xv = xs4[j];
            kah(s, comp, __fmul_rn(xv.x, wv.x));
            kah(s, comp, __fmul_rn(xv.y, wv.y));
            kah(s, comp, __fmul_rn(xv.z, wv.z));
            kah(s, comp, __fmul_rn(xv.w, wv.w));
        }
        double d = (double)s + (double)comp;
#pragma unroll
        for (int off = 16; off > 0; off >>= 1)
            d += __shfl_down_sync(0xffffffffu, d, off);
        if (lane == 0) {
            float sc = (float)(d + (double)bias[fi]);
            key[c] = ((unsigned long long)f2ord(sc) << 32) |
                     (unsigned long long)(unsigned)(16383 - fi);
        }
    }
    __syncthreads();

    // sort 1: exact value desc (idx asc ties) -> top-k
    for (int kk = 2; kk <= 256; kk <<= 1) {
        for (int j = kk >> 1; j > 0; j >>= 1) {
            int ixj = tid ^ j;
            if (ixj > tid) {
                unsigned long long a = key[tid], bb2 = key[ixj];
                bool up = ((tid & kk) == 0);
                if (up ? (a < bb2) : (a > bb2)) { key[tid] = bb2; key[ixj] = a; }
            }
            __syncthreads();
        }
    }

    unsigned my_idx = 0; float my_zv = 0.0f;
    if (tid < k) {
        unsigned long long kv = key[tid];
        my_idx = 16383u - (unsigned)(kv & 0xFFFFull);
        my_zv = fmaxf(ord2f((unsigned)(kv >> 32)), 0.0f);
        z[(size_t)b * GN + my_idx] = my_zv;
    }
    __syncthreads();

    // sort 2: top-k by feature index asc (L2-friendly decode order)
    key[tid] = (tid < k)
        ? (((unsigned long long)my_idx << 32) | (unsigned)__float_as_uint(my_zv))
        : 0xFFFFFFFFFFFFFFFFull;
    __syncthreads();
    for (int kk = 2; kk <= 256; kk <<= 1) {
        for (int j = kk >> 1; j > 0; j >>= 1) {
            int ixj = tid ^ j;
            if (ixj > tid) {
                unsigned long long a = key[tid], bb2 = key[ixj];
                bool up = ((tid & kk) == 0);
                if (up ? (a > bb2) : (a < bb2)) { key[tid] = bb2; key[ixj] = a; }
            }
            __syncthreads();
        }
    }
    if (tid < k) {
        g_topk_idx[b * 256 + tid] = (int)(key[tid] >> 32);
        g_topk_val[b * 256 + tid] = __uint_as_float((unsigned)key[tid]);
    }
}

// ---------------- sparse decode + loss (index-ordered, x4 unrolled) ---------
__global__ __launch_bounds__(TPB)
void decode_kernel(const float* __restrict__ W_dec, const float* __restrict__ b_dec,
                   const float* __restrict__ x, const int* __restrict__ kptr,
                   float* __restrict__ x_hat, int n_td)
{
    const int b = blockIdx.x, tid = threadIdx.x;
    const int k = kptr[0];
    __shared__ int s_idx[256];
    __shared__ float s_val[256];
    if (tid < k) { s_idx[tid] = g_topk_idx[b * 256 + tid]; s_val[tid] = g_topk_val[b * 256 + tid]; }
    __syncthreads();

    float4 acc[3];
#pragma unroll
    for (int q = 0; q < 3; q++) acc[q] = make_float4(0.f, 0.f, 0.f, 0.f);

    int j = 0;
    for (; j + 4 <= k; j += 4) {
        const float v0 = s_val[j], v1 = s_val[j + 1], v2 = s_val[j + 2], v3 = s_val[j + 3];
        const float4* w0 = (const float4*)(W_dec + (size_t)s_idx[j] * n_td);
        const float4* w1 = (const float4*)(W_dec + (size_t)s_idx[j + 1] * n_td);
        const float4* w2 = (const float4*)(W_dec + (size_t)s_idx[j + 2] * n_td);
        const float4* w3 = (const float4*)(W_dec + (size_t)s_idx[j + 3] * n_td);
#pragma unroll
        for (int q = 0; q < 3; q++) {
            int p = tid + 256 * q;
            float4 a0 = __ldg(&w0[p]);
            float4 a1 = __ldg(&w1[p]);
            float4 a2 = __ldg(&w2[p]);
            float4 a3 = __ldg(&w3[p]);
            acc[q].x = fmaf(v0, a0.x, acc[q].x); acc[q].y = fmaf(v0, a0.y, acc[q].y);
            acc[q].z = fmaf(v0, a0.z, acc[q].z); acc[q].w = fmaf(v0, a0.w, acc[q].w);
            acc[q].x = fmaf(v1, a1.x, acc[q].x); acc[q].y = fmaf(v1, a1.y, acc[q].y);
            acc[q].z = fmaf(v1, a1.z, acc[q].z); acc[q].w = fmaf(v1, a1.w, acc[q].w);
            acc[q].x = fmaf(v2, a2.x, acc[q].x); acc[q].y = fmaf(v2, a2.y, acc[q].y);
            acc[q].z = fmaf(v2, a2.z, acc[q].z); acc[q].w = fmaf(v2, a2.w, acc[q].w);
            acc[q].x = fmaf(v3, a3.x, acc[q].x); acc[q].y = fmaf(v3, a3.y, acc[q].y);
            acc[q].z = fmaf(v3, a3.z, acc[q].z); acc[q].w = fmaf(v3, a3.w, acc[q].w);
        }
    }
    for (; j < k; j++) {
        const float v = s_val[j];
        const float4* w = (const float4*)(W_dec + (size_t)s_idx[j] * n_td);
#pragma unroll
        for (int q = 0; q < 3; q++) {
            float4 wv = __ldg(&w[tid + 256 * q]);
            acc[q].x = fmaf(v, wv.x, acc[q].x); acc[q].y = fmaf(v, wv.y, acc[q].y);
            acc[q].z = fmaf(v, wv.z, acc[q].z); acc[q].w = fmaf(v, wv.w, acc[q].w);
        }
    }

    const float4* x4 = (const float4*)(x + (size_t)b * n_td);
    const float4* bd4 = (const float4*)b_dec;
    float* xh = x_hat + (size_t)b * n_td;   // 4B-aligned only
    float sq = 0.0f;
#pragma unroll
    for (int q = 0; q < 3; q++) {
        int p = tid + 256 * q;
        float4 bb = bd4[p], xx = x4[p];
        float ox = acc[q].x + bb.x, oy = acc[q].y + bb.y;
        float oz = acc[q].z + bb.z, ow = acc[q].w + bb.w;
        xh[p * 4 + 0] = ox; xh[p * 4 + 1] = oy; xh[p * 4 + 2] = oz; xh[p * 4 + 3] = ow;
        float dx = ox - xx.x, dy = oy - xx.y, dz = oz - xx.z, dw = ow - xx.w;
        sq += dx * dx + dy * dy + dz * dz + dw * dw;
    }
    __shared__ float red[TPB];
    red[tid] = sq; __syncthreads();
    for (int s = TPB / 2; s > 0; s >>= 1) {
        if (tid < s) red[tid] += red[tid + s];
        __syncthreads();
    }
    if (tid == 0) g_partial[b] = red[0];
}

__global__ __launch_bounds__(TPB)
void finalize_kernel(int M, float inv_bt, float* __restrict__ out_loss)
{
    __shared__ float red[TPB];
    const int tid = threadIdx.x;
    float s = 0.0f;
    for (int i = tid; i < M; i += TPB) s += g_partial[i];
    red[tid] = s; __syncthreads();
    for (int st = TPB / 2; st > 0; st >>= 1) {
        if (tid < st) red[tid] += red[tid + st];
        __syncthreads();
    }
    if (tid == 0) out_loss[0] = red[0] * inv_bt;
}

// ---------------- host ----------------
extern "C" void kernel_launch(void* const* d_in, const int* in_sizes, int n_in,
                              void* d_out, int out_size)
{
    const float* x     = (const float*)d_in[0];
    const float* W_enc = (const float*)d_in[1];
    const float* b_enc = (const float*)d_in[2];
    const float* W_dec = (const float*)d_in[3];
    const float* b_dec = (const float*)d_in[4];
    const int*   kptr  = (const int*)d_in[5];

    float* out      = (float*)d_out;
    float* out_loss = out;
    float* out_xhat = out + 1;
    float* out_z    = out + 1 + (size_t)GM * 3072;

    static bool once = false;
    if (!once) {
        cudaFuncSetAttribute(mma_gemm_kernel,
                             cudaFuncAttributeMaxDynamicSharedMemorySize, GEMM_SMEM);
        cudaFuncSetAttribute(topk_rerank_kernel,
                             cudaFuncAttributeMaxDynamicSharedMemorySize, SMEM_TOPK);
        once = true;
    }

    prep_kernel<<<dim3(GN / 32, GK / 32), dim3(32, 8)>>>(x, W_enc);        // 0
    mma_gemm_kernel<<<dim3(GM / BM, GN / BN), 256, GEMM_SMEM>>>();         // 1
    zzero_kernel<<<2048, 256>>>(out_z);                                    // 2
    topk_rerank_kernel<<<GM, TPB, SMEM_TOPK>>>(x, b_enc, kptr, out_z);     // 3 -> profiled
    decode_kernel<<<GM, TPB>>>(W_dec, b_dec, x, kptr, out_xhat, 3072);     // 4
    finalize_kernel<<<1, TPB>>>(GM, 1.0f / 8192.0f, out_loss);             // 5
}

// round 16
// speedup vs baseline: 1.2804x; 1.2804x over previous
#include <cuda_runtime.h>
#include <cuda_bf16.h>
#include <cstdint>

#define TPB 256
#define GM 2048
#define GN 16384
#define GK 3072

#define BM 128
#define BN 128
#define BK 64
#define NKT (GK / BK)           // 48
#define A_TILE_B (BM * 128)
#define B_TILE_B (BN * 128)
#define STG_B (A_TILE_B + B_TILE_B)
#define GEMM_SMEM (3 * STG_B)   // 98304 -> 2 CTAs/SM

__device__ float g_pre[(size_t)GM * GN];
__device__ float g_Bt[(size_t)GN * GK];
__device__ __nv_bfloat16 g_Btb[(size_t)GN * GK];
__device__ __nv_bfloat16 g_Ab[(size_t)GM * GK];
__device__ int   g_topk_idx[GM * 256];
__device__ float g_topk_val[GM * 256];
__device__ float g_partial[GM];

// ---------------- helpers ----------------
__device__ __forceinline__ void mma_bf16(float* c, const uint32_t* a, const uint32_t* b) {
    asm volatile(
        "mma.sync.aligned.m16n8k16.row.col.f32.bf16.bf16.f32 "
        "{%0,%1,%2,%3}, {%4,%5,%6,%7}, {%8,%9}, {%0,%1,%2,%3};"
        : "+f"(c[0]), "+f"(c[1]), "+f"(c[2]), "+f"(c[3])
        : "r"(a[0]), "r"(a[1]), "r"(a[2]), "r"(a[3]), "r"(b[0]), "r"(b[1]));
}
__device__ __forceinline__ void ldsm_x4(uint32_t& r0, uint32_t& r1, uint32_t& r2,
                                        uint32_t& r3, uint32_t addr) {
    asm volatile("ldmatrix.sync.aligned.m8n8.x4.shared.b16 {%0,%1,%2,%3}, [%4];"
                 : "=r"(r0), "=r"(r1), "=r"(r2), "=r"(r3) : "r"(addr));
}
__device__ __forceinline__ void bulk_g2s(uint32_t dst, const void* src,
                                         uint32_t bytes, uint32_t bar) {
    asm volatile(
        "cp.async.bulk.shared::cluster.global.mbarrier::complete_tx::bytes "
        "[%0], [%1], %2, [%3];"
        :: "r"(dst), "l"(src), "r"(bytes), "r"(bar) : "memory");
}
__device__ __forceinline__ uint32_t smem_u32(const void* p) {
    uint32_t a;
    asm("{ .reg .u64 t; cvta.to.shared.u64 t, %1; cvt.u32.u64 %0, t; }" : "=r"(a) : "l"(p));
    return a;
}
__device__ __forceinline__ void mbar_init(uint32_t a, uint32_t c) {
    asm volatile("mbarrier.init.shared.b64 [%0], %1;" :: "r"(a), "r"(c) : "memory");
}
__device__ __forceinline__ void mbar_expect_tx(uint32_t a, uint32_t bytes) {
    asm volatile("mbarrier.arrive.expect_tx.shared.b64 _, [%0], %1;" :: "r"(a), "r"(bytes) : "memory");
}
__device__ __forceinline__ void mbar_arrive(uint32_t a) {
    asm volatile("mbarrier.arrive.shared.b64 _, [%0];" :: "r"(a) : "memory");
}
__device__ __forceinline__ void mbar_wait(uint32_t a, uint32_t parity) {
    asm volatile(
        "{\n\t.reg .pred P;\nW_%=:\n\t"
        "mbarrier.try_wait.parity.acquire.cta.shared::cta.b64 P, [%0], %1, 0x989680;\n\t"
        "@P bra.uni D_%=;\n\tbra.uni W_%=;\nD_%=:\n\t}"
        :: "r"(a), "r"(parity) : "memory");
}
__device__ __forceinline__ void mbar_wait_rlx(uint32_t a, uint32_t parity) {
    asm volatile(
        "{\n\t.reg .pred P;\nW_%=:\n\t"
        "mbarrier.try_wait.parity.relaxed.cta.shared::cta.b64 P, [%0], %1, 0x989680;\n\t"
        "@P bra.uni D_%=;\n\tbra.uni W_%=;\nD_%=:\n\t}"
        :: "r"(a), "r"(parity) : "memory");
}
__device__ __forceinline__ unsigned f2ord(float f) {
    unsigned u = __float_as_uint(f);
    return (u & 0x80000000u) ? ~u : (u | 0x80000000u);
}
__device__ __forceinline__ float ord2f(unsigned o) {
    unsigned u = (o & 0x80000000u) ? (o & 0x7FFFFFFFu) : ~o;
    return __uint_as_float(u);
}
__device__ __forceinline__ void kah(float& s, float& c, float p) {
    float y = __fsub_rn(p, c);
    float t = __fadd_rn(s, y);
    c = __fsub_rn(__fsub_rn(t, s), y);
    s = t;
}
__device__ __forceinline__ uint32_t pack_bf2(float a, float b) {
    __nv_bfloat162 h = __floats2bfloat162_rn(a, b);
    return *(uint32_t*)&h;
}

// ---------------- prep: A conv (bf16 tiled) + W_enc transpose (fp32 + bf16) -
__global__ __launch_bounds__(256)
void prep_kernel(const float* __restrict__ x, const float* __restrict__ W) {
    __shared__ float t[32][33];
    const int n0 = blockIdx.x * 32, k0 = blockIdx.y * 32;
    const int tx = threadIdx.x, ty = threadIdx.y;
    const int tid = ty * 32 + tx;
    const int bid = blockIdx.y * gridDim.x + blockIdx.x;

    {
        const int nch = GM * GK / 8;
        int i = bid * 256 + tid;
        if (i < nch) {
            int m = i / (GK / 8);
            int kc8 = i - m * (GK / 8);
            const float4* src = (const float4*)(x + (size_t)m * GK + kc8 * 8);
            float4 v0 = src[0], v1 = src[1];
            uint4 p = make_uint4(pack_bf2(v0.x, v0.y), pack_bf2(v0.z, v0.w),
                                 pack_bf2(v1.x, v1.y), pack_bf2(v1.z, v1.w));
            int m_blk = m >> 7, row = m & 127;
            int k_blk = kc8 >> 3, ch = kc8 & 7;
            size_t off = ((size_t)(m_blk * NKT + k_blk) * 128 + row) * 128
                       + ((ch ^ (row & 7)) << 4);
            *(uint4*)((char*)g_Ab + off) = p;
        }
    }

#pragma unroll
    for (int i = 0; i < 4; i++)
        t[ty + i * 8][tx] = W[(size_t)(k0 + ty + i * 8) * GN + n0 + tx];
    __syncthreads();
#pragma unroll
    for (int i = 0; i < 4; i++)
        g_Bt[(size_t)(n0 + ty + i * 8) * GK + k0 + tx] = t[tx][ty + i * 8];

    char* dst = (char*)g_Btb;
    for (int it = tid; it < 32 * 4; it += 256) {
        int nl = it >> 2, c = it & 3;
        int n = n0 + nl;
        uint32_t w[4];
#pragma unroll
        for (int j = 0; j < 4; j++)
            w[j] = pack_bf2(t[c * 8 + j * 2][nl], t[c * 8 + j * 2 + 1][nl]);
        int n_blk = n >> 7, row = n & 127;
        int k_blk = k0 >> 6;
        int ch = ((k0 & 63) >> 3) + c;
        size_t off = ((size_t)(n_blk * NKT + k_blk) * 128 + row) * 128
                   + ((ch ^ (row & 7)) << 4);
        *(uint4*)(dst + off) = make_uint4(w[0], w[1], w[2], w[3]);
    }
}

// ---------------- coarse GEMM (R10-proven: 435us, tensor 78%) ---------------
__global__ __launch_bounds__(256, 2)
void mma_gemm_kernel()
{
    extern __shared__ char smc[];
    __shared__ uint64_t barmem[6];
    const uint32_t sb = smem_u32(smc);
    const uint32_t bb = smem_u32(barmem);
    const int tid = threadIdx.x;
    const int lane = tid & 31;
    const int wid = tid >> 5;
    const int wm = wid & 1;
    const int wn = wid >> 1;

    if (tid == 0) {
#pragma unroll
        for (int s = 0; s < 3; s++) {
            mbar_init(bb + s * 8, 1);
            mbar_init(bb + 24 + s * 8, 256);
        }
    }
    __syncthreads();

    const char* Ag = (const char*)g_Ab + (size_t)blockIdx.x * NKT * A_TILE_B;
    const char* Bg = (const char*)g_Btb + (size_t)blockIdx.y * NKT * B_TILE_B;

    if (tid == 0) {
#pragma unroll
        for (int kt = 0; kt < 3; kt++) {
            mbar_expect_tx(bb + kt * 8, STG_B);
            bulk_g2s(sb + kt * STG_B, Ag + (size_t)kt * A_TILE_B, A_TILE_B, bb + kt * 8);
            bulk_g2s(sb + kt * STG_B + A_TILE_B, Bg + (size_t)kt * B_TILE_B, B_TILE_B, bb + kt * 8);
        }
    }

    float acc[4][4][4];
#pragma unroll
    for (int i = 0; i < 4; i++)
#pragma unroll
        for (int j = 0; j < 4; j++)
#pragma unroll
            for (int q = 0; q < 4; q++) acc[i][j][q] = 0.0f;

    uint32_t arow[4], brow[2];
#pragma unroll
    for (int mi = 0; mi < 4; mi++) {
        int r = wm * 64 + mi * 16 + (lane & 15);
        arow[mi] = (uint32_t)(r * 128) | ((uint32_t)(r & 7) << 24);
    }
#pragma unroll
    for (int nj = 0; nj < 2; nj++) {
        int r = wn * 32 + nj * 16 + (lane & 7) + ((lane >> 4) << 3);
        brow[nj] = (uint32_t)(r * 128) | ((uint32_t)(r & 7) << 24);
    }
    const uint32_t achunk = (uint32_t)(lane >> 4);
    const uint32_t bchunk = (uint32_t)((lane >> 3) & 1);

    for (int kt = 0; kt < NKT; kt++) {
        const int s = kt - (kt / 3) * 3;
        const int u = kt / 3;
        mbar_wait(bb + s * 8, u & 1);

        const uint32_t Ab = sb + s * STG_B;
        const uint32_t Bb = Ab + A_TILE_B;

#pragma unroll
        for (int ks = 0; ks < 4; ks++) {
            uint32_t af[4][4], bf[4][2];
#pragma unroll
            for (int mi = 0; mi < 4; mi++) {
                uint32_t swz = arow[mi] >> 24;
                uint32_t ch = (uint32_t)(ks * 2) + achunk;
                uint32_t addr = Ab + (arow[mi] & 0xFFFFFFu) + ((ch ^ swz) << 4);
                ldsm_x4(af[mi][0], af[mi][1], af[mi][2], af[mi][3], addr);
            }
#pragma unroll
            for (int nj = 0; nj < 2; nj++) {
                uint32_t swz = brow[nj] >> 24;
                uint32_t ch = (uint32_t)(ks * 2) + bchunk;
                uint32_t addr = Bb + (brow[nj] & 0xFFFFFFu) + ((ch ^ swz) << 4);
                ldsm_x4(bf[nj * 2][0], bf[nj * 2][1], bf[nj * 2 + 1][0], bf[nj * 2 + 1][1], addr);
            }
#pragma unroll
            for (int mi = 0; mi < 4; mi++)
#pragma unroll
                for (int ni = 0; ni < 4; ni++)
                    mma_bf16(acc[mi][ni], af[mi], bf[ni]);
        }

        mbar_arrive(bb + 24 + s * 8);
        if (tid == 0 && kt + 3 < NKT) {
            mbar_wait_rlx(bb + 24 + s * 8, u & 1);
            mbar_expect_tx(bb + s * 8, STG_B);
            bulk_g2s(sb + s * STG_B, Ag + (size_t)(kt + 3) * A_TILE_B, A_TILE_B, bb + s * 8);
            bulk_g2s(sb + s * STG_B + A_TILE_B, Bg + (size_t)(kt + 3) * B_TILE_B, B_TILE_B, bb + s * 8);
        }
    }

    const int m0 = blockIdx.x * BM, n0 = blockIdx.y * BN;
#pragma unroll
    for (int mi = 0; mi < 4; mi++)
#pragma unroll
        for (int ni = 0; ni < 4; ni++) {
            int r = m0 + wm * 64 + mi * 16 + (lane >> 2);
            int c = n0 + wn * 32 + ni * 8 + (lane & 3) * 2;
            *(float2*)(g_pre + (size_t)r * GN + c) = make_float2(acc[mi][ni][0], acc[mi][ni][1]);
            *(float2*)(g_pre + (size_t)(r + 8) * GN + c) = make_float2(acc[mi][ni][2], acc[mi][ni][3]);
        }
}

// ---------------- z zeroing (slot 2) ----------------
__global__ __launch_bounds__(256)
void zzero_kernel(float* __restrict__ z) {
    const size_t n = (size_t)GM * GN;
    for (size_t i = (size_t)blockIdx.x * blockDim.x + threadIdx.x; i < n;
         i += (size_t)gridDim.x * blockDim.x)
        z[i] = 0.0f;
}

// ---------------- fused select + rerank: low-smem (25KB) high-occupancy -----
// Keys are recomputed from g_pre (L2-resident per row) on each pass instead of
// cached in smem: 6 CTAs/SM instead of 2 -> 3x latency hiding.
__global__ __launch_bounds__(TPB, 6)
void topk_rerank_kernel(const float* __restrict__ x, const float* __restrict__ bias,
                        const int* __restrict__ kptr, float* __restrict__ z)
{
    __shared__ __align__(16) float xs[GK];                   // 12288 B
    __shared__ __align__(16) unsigned long long key[256];    // 2048 B
    __shared__ unsigned hist[2048];                          // 8192 B
    __shared__ int cidx[256];                                // 1024 B
    __shared__ int scan[256];                                // 1024 B
    __shared__ int sT1, sC1, sT2, sC2, sCnt2, sNgt, sNmid, sNeq;

    const int b = blockIdx.x;
    const int tid = threadIdx.x;
    const int lane = tid & 31;
    const int wrp = tid >> 5;
    const int k = kptr[0];
    const int kc = min(k + 32, 256);

    const float4* row4 = (const float4*)(g_pre + (size_t)b * GN);
    const float4* b4 = (const float4*)bias;

#pragma unroll
    for (int q = 0; q < 8; q++) hist[tid + q * 256] = 0u;
    key[tid] = 0ull;
    if (tid == 0) { sNgt = 0; sNmid = 0; sNeq = 0; }
    {
        const float4* xg = (const float4*)(x + (size_t)b * GK);
#pragma unroll
        for (int q = 0; q < 3; q++) ((float4*)xs)[tid + 256 * q] = xg[tid + 256 * q];
    }
    __syncthreads();

    // pass 1: level-1 histogram (top 11 bits); keys recomputed, not stored
#pragma unroll
    for (int q = 0; q < 16; q++) {
        int i4 = tid + q * 256;
        float4 r = row4[i4];
        float4 bb = __ldg(&b4[i4]);
        atomicAdd(&hist[f2ord(r.x + bb.x) >> 21], 1u);
        atomicAdd(&hist[f2ord(r.y + bb.y) >> 21], 1u);
        atomicAdd(&hist[f2ord(r.z + bb.z) >> 21], 1u);
        atomicAdd(&hist[f2ord(r.w + bb.w) >> 21], 1u);
    }
    __syncthreads();

    // level-1 threshold bin T1
    {
        int s = 0;
#pragma unroll
        for (int j = 0; j < 8; j++) s += (int)hist[2047 - 8 * tid - j];
        scan[tid] = s;
    }
    __syncthreads();
    if (tid == 0) {
        int acc = 0;
        for (int t = 0; t < 256; t++) { int v = scan[t]; scan[t] = acc; acc += v; }
    }
    __syncthreads();
    {
        int cum = scan[tid];
#pragma unroll
        for (int j = 0; j < 8; j++) {
            int bn = 2047 - 8 * tid - j;
            int c = (int)hist[bn];
            if (cum < kc && cum + c >= kc) { sT1 = bn; sC1 = cum; }
            cum += c;
        }
    }
    __syncthreads();
    const unsigned T1 = (unsigned)sT1;
    const int C1 = sC1;
    const int need2 = kc - C1;   // >= 1

    // pass 1b: level-2 histogram over bucket-T1 elements (bits 20:10)
#pragma unroll
    for (int q = 0; q < 8; q++) hist[tid + q * 256] = 0u;
    __syncthreads();
#pragma unroll
    for (int q = 0; q < 16; q++) {
        int i4 = tid + q * 256;
        float4 r = row4[i4];
        float4 bb = __ldg(&b4[i4]);
        unsigned u0 = f2ord(r.x + bb.x);
        unsigned u1 = f2ord(r.y + bb.y);
        unsigned u2 = f2ord(r.z + bb.z);
        unsigned u3 = f2ord(r.w + bb.w);
        if ((u0 >> 21) == T1) atomicAdd(&hist[(u0 >> 10) & 2047u], 1u);
        if ((u1 >> 21) == T1) atomicAdd(&hist[(u1 >> 10) & 2047u], 1u);
        if ((u2 >> 21) == T1) atomicAdd(&hist[(u2 >> 10) & 2047u], 1u);
        if ((u3 >> 21) == T1) atomicAdd(&hist[(u3 >> 10) & 2047u], 1u);
    }
    __syncthreads();

    // level-2 threshold sub-bin T2
    {
        int s = 0;
#pragma unroll
        for (int j = 0; j < 8; j++) s += (int)hist[2047 - 8 * tid - j];
        scan[tid] = s;
    }
    __syncthreads();
    if (tid == 0) {
        int acc = 0;
        for (int t = 0; t < 256; t++) { int v = scan[t]; scan[t] = acc; acc += v; }
    }
    __syncthreads();
    {
        int cum = scan[tid];
#pragma unroll
        for (int j = 0; j < 8; j++) {
            int bn = 2047 - 8 * tid - j;
            int c = (int)hist[bn];
            if (cum < need2 && cum + c >= need2) { sT2 = bn; sC2 = cum; sCnt2 = c; }
            cum += c;
        }
    }
    __syncthreads();
    const unsigned T2 = (unsigned)sT2;
    const int C2 = sC2;
    const int kact = min(C1 + C2 + sCnt2, 256);
    const int cap_eq = kact - C1 - C2;

    // pass 2: compaction (>T1 | T1&&>T2 | T1&&==T2 capped)
#pragma unroll
    for (int q = 0; q < 16; q++) {
        int i4 = tid + q * 256;
        float4 r = row4[i4];
        float4 bb = __ldg(&b4[i4]);
        unsigned uu[4] = { f2ord(r.x + bb.x), f2ord(r.y + bb.y),
                           f2ord(r.z + bb.z), f2ord(r.w + bb.w) };
        int e0 = i4 * 4;
#pragma unroll
        for (int e = 0; e < 4; e++) {
            unsigned bn = uu[e] >> 21;
            if (bn > T1) cidx[atomicAdd(&sNgt, 1)] = e0 + e;
            else if (bn == T1) {
                unsigned sub = (uu[e] >> 10) & 2047u;
                if (sub > T2) cidx[C1 + atomicAdd(&sNmid, 1)] = e0 + e;
                else if (sub == T2) {
                    int er = atomicAdd(&sNeq, 1);
                    if (er < cap_eq) cidx[C1 + C2 + er] = e0 + e;
                }
            }
        }
    }
    __syncthreads();

    // exact rerank (dual Kahan chains for ILP + double reduce)
    const float4* xs4 = (const float4*)xs;
    for (int c = wrp; c < kact; c += 8) {
        const int fi = cidx[c];
        const float4* wr = (const float4*)(g_Bt + (size_t)fi * GK);
        float s0 = 0.0f, c0 = 0.0f, s1 = 0.0f, c1 = 0.0f;
#pragma unroll 4
        for (int it = 0; it < 24; it += 2) {
            int ja = lane + it * 32;
            int jb = ja + 32;
            float4 wa = wr[ja], xa = xs4[ja];
            float4 wb = wr[jb], xb = xs4[jb];
            kah(s0, c0, __fmul_rn(xa.x, wa.x));
            kah(s1, c1, __fmul_rn(xb.x, wb.x));
            kah(s0, c0, __fmul_rn(xa.y, wa.y));
            kah(s1, c1, __fmul_rn(xb.y, wb.y));
            kah(s0, c0, __fmul_rn(xa.z, wa.z));
            kah(s1, c1, __fmul_rn(xb.z, wb.z));
            kah(s0, c0, __fmul_rn(xa.w, wa.w));
            kah(s1, c1, __fmul_rn(xb.w, wb.w));
        }
        double d = ((double)s0 + (double)c0) + ((double)s1 + (double)c1);
#pragma unroll
        for (int off = 16; off > 0; off >>= 1)
            d += __shfl_down_sync(0xffffffffu, d, off);
        if (lane == 0) {
            float sc = (float)(d + (double)bias[fi]);
            key[c] = ((unsigned long long)f2ord(sc) << 32) |
                     (unsigned long long)(unsigned)(16383 - fi);
        }
    }
    __syncthreads();

    // sort 1: exact value desc (idx asc ties) -> top-k
    for (int kk = 2; kk <= 256; kk <<= 1) {
        for (int j = kk >> 1; j > 0; j >>= 1) {
            int ixj = tid ^ j;
            if (ixj > tid) {
                unsigned long long a = key[tid], bb2 = key[ixj];
                bool up = ((tid & kk) == 0);
                if (up ? (a < bb2) : (a > bb2)) { key[tid] = bb2; key[ixj] = a; }
            }
            __syncthreads();
        }
    }

    unsigned my_idx = 0; float my_zv = 0.0f;
    if (tid < k) {
        unsigned long long kv = key[tid];
        my_idx = 16383u - (unsigned)(kv & 0xFFFFull);
        my_zv = fmaxf(ord2f((unsigned)(kv >> 32)), 0.0f);
        z[(size_t)b * GN + my_idx] = my_zv;
    }
    __syncthreads();

    // sort 2: top-k by feature index asc (L2-friendly decode order)
    key[tid] = (tid < k)
        ? (((unsigned long long)my_idx << 32) | (unsigned)__float_as_uint(my_zv))
        : 0xFFFFFFFFFFFFFFFFull;
    __syncthreads();
    for (int kk = 2; kk <= 256; kk <<= 1) {
        for (int j = kk >> 1; j > 0; j >>= 1) {
            int ixj = tid ^ j;
            if (ixj > tid) {
                unsigned long long a = key[tid], bb2 = key[ixj];
                bool up = ((tid & kk) == 0);
                if (up ? (a > bb2) : (a < bb2)) { key[tid] = bb2; key[ixj] = a; }
            }
            __syncthreads();
        }
    }
    if (tid < k) {
        g_topk_idx[b * 256 + tid] = (int)(key[tid] >> 32);
        g_topk_val[b * 256 + tid] = __uint_as_float((unsigned)key[tid]);
    }
}

// ---------------- sparse decode + loss (index-ordered, x4 unrolled) ---------
__global__ __launch_bounds__(TPB)
void decode_kernel(const float* __restrict__ W_dec, const float* __restrict__ b_dec,
                   const float* __restrict__ x, const int* __restrict__ kptr,
                   float* __restrict__ x_hat, int n_td)
{
    const int b = blockIdx.x, tid = threadIdx.x;
    const int k = kptr[0];
    __shared__ int s_idx[256];
    __shared__ float s_val[256];
    if (tid < k) { s_idx[tid] = g_topk_idx[b * 256 + tid]; s_val[tid] = g_topk_val[b * 256 + tid]; }
    __syncthreads();

    float4 acc[3];
#pragma unroll
    for (int q = 0; q < 3; q++) acc[q] = make_float4(0.f, 0.f, 0.f, 0.f);

    int j = 0;
    for (; j + 4 <= k; j += 4) {
        const float v0 = s_val[j], v1 = s_val[j + 1], v2 = s_val[j + 2], v3 = s_val[j + 3];
        const float4* w0 = (const float4*)(W_dec + (size_t)s_idx[j] * n_td);
        const float4* w1 = (const float4*)(W_dec + (size_t)s_idx[j + 1] * n_td);
        const float4* w2 = (const float4*)(W_dec + (size_t)s_idx[j + 2] * n_td);
        const float4* w3 = (const float4*)(W_dec + (size_t)s_idx[j + 3] * n_td);
#pragma unroll
        for (int q = 0; q < 3; q++) {
            int p = tid + 256 * q;
            float4 a0 = __ldg(&w0[p]);
            float4 a1 = __ldg(&w1[p]);
            float4 a2 = __ldg(&w2[p]);
            float4 a3 = __ldg(&w3[p]);
            acc[q].x = fmaf(v0, a0.x, acc[q].x); acc[q].y = fmaf(v0, a0.y, acc[q].y);
            acc[q].z = fmaf(v0, a0.z, acc[q].z); acc[q].w = fmaf(v0, a0.w, acc[q].w);
            acc[q].x = fmaf(v1, a1.x, acc[q].x); acc[q].y = fmaf(v1, a1.y, acc[q].y);
            acc[q].z = fmaf(v1, a1.z, acc[q].z); acc[q].w = fmaf(v1, a1.w, acc[q].w);
            acc[q].x = fmaf(v2, a2.x, acc[q].x); acc[q].y = fmaf(v2, a2.y, acc[q].y);
            acc[q].z = fmaf(v2, a2.z, acc[q].z); acc[q].w = fmaf(v2, a2.w, acc[q].w);
            acc[q].x = fmaf(v3, a3.x, acc[q].x); acc[q].y = fmaf(v3, a3.y, acc[q].y);
            acc[q].z = fmaf(v3, a3.z, acc[q].z); acc[q].w = fmaf(v3, a3.w, acc[q].w);
        }
    }
    for (; j < k; j++) {
        const float v = s_val[j];
        const float4* w = (const float4*)(W_dec + (size_t)s_idx[j] * n_td);
#pragma unroll
        for (int q = 0; q < 3; q++) {
            float4 wv = __ldg(&w[tid + 256 * q]);
            acc[q].x = fmaf(v, wv.x, acc[q].x); acc[q].y = fmaf(v, wv.y, acc[q].y);
            acc[q].z = fmaf(v, wv.z, acc[q].z); acc[q].w = fmaf(v, wv.w, acc[q].w);
        }
    }

    const float4* x4 = (const float4*)(x + (size_t)b * n_td);
    const float4* bd4 = (const float4*)b_dec;
    float* xh = x_hat + (size_t)b * n_td;   // 4B-aligned only
    float sq = 0.0f;
#pragma unroll
    for (int q = 0; q < 3; q++) {
        int p = tid + 256 * q;
        float4 bb = bd4[p], xx = x4[p];
        float ox = acc[q].x + bb.x, oy = acc[q].y + bb.y;
        float oz = acc[q].z + bb.z, ow = acc[q].w + bb.w;
        xh[p * 4 + 0] = ox; xh[p * 4 + 1] = oy; xh[p * 4 + 2] = oz; xh[p * 4 + 3] = ow;
        float dx = ox - xx.x, dy = oy - xx.y, dz = oz - xx.z, dw = ow - xx.w;
        sq += dx * dx + dy * dy + dz * dz + dw * dw;
    }
    __shared__ float red[TPB];
    red[tid] = sq; __syncthreads();
    for (int s = TPB / 2; s > 0; s >>= 1) {
        if (tid < s) red[tid] += red[tid + s];
        __syncthreads();
    }
    if (tid == 0) g_partial[b] = red[0];
}

__global__ __launch_bounds__(TPB)
void finalize_kernel(int M, float inv_bt, float* __restrict__ out_loss)
{
    __shared__ float red[TPB];
    const int tid = threadIdx.x;
    float s = 0.0f;
    for (int i = tid; i < M; i += TPB) s += g_partial[i];
    red[tid] = s; __syncthreads();
    for (int st = TPB / 2; st > 0; st >>= 1) {
        if (tid < st) red[tid] += red[tid + st];
        __syncthreads();
    }
    if (tid == 0) out_loss[0] = red[0] * inv_bt;
}

// ---------------- host ----------------
extern "C" void kernel_launch(void* const* d_in, const int* in_sizes, int n_in,
                              void* d_out, int out_size)
{
    const float* x     = (const float*)d_in[0];
    const float* W_enc = (const float*)d_in[1];
    const float* b_enc = (const float*)d_in[2];
    const float* W_dec = (const float*)d_in[3];
    const float* b_dec = (const float*)d_in[4];
    const int*   kptr  = (const int*)d_in[5];

    float* out      = (float*)d_out;
    float* out_loss = out;
    float* out_xhat = out + 1;
    float* out_z    = out + 1 + (size_t)GM * 3072;

    static bool once = false;
    if (!once) {
        cudaFuncSetAttribute(mma_gemm_kernel,
                             cudaFuncAttributeMaxDynamicSharedMemorySize, GEMM_SMEM);
        once = true;
    }

    prep_kernel<<<dim3(GN / 32, GK / 32), dim3(32, 8)>>>(x, W_enc);        // 0
    mma_gemm_kernel<<<dim3(GM / BM, GN / BN), 256, GEMM_SMEM>>>();         // 1
    zzero_kernel<<<2048, 256>>>(out_z);                                    // 2
    topk_rerank_kernel<<<GM, TPB>>>(x, b_enc, kptr, out_z);                // 3 -> profiled
    decode_kernel<<<GM, TPB>>>(W_dec, b_dec, x, kptr, out_xhat, 3072);     // 4
    finalize_kernel<<<1, TPB>>>(GM, 1.0f / 8192.0f, out_loss);             // 5
}